// round 8
// baseline (speedup 1.0000x reference)
#include <cuda_runtime.h>
#include <cuda_bf16.h>
#include <cuda_fp16.h>
#include <cstdint>

#define NTOK 16384
#define DIN  512
#define NB   8
#define KR   4608                 // real K = 512*9
#define KE   13824                // 3 regions: [bf16 hi | fp16 lo | fp16 hi]
#define BK   64                   // K per stage = 128 bytes/row
#define NST  216                  // total stages
#define NF16 144                  // fp16-acc stages (regions 2+3, processed first)
#define STAGE_BYTES 49152         // A 32KB + B 16KB
#define CTA_M 256
#define CTA_N 128

// Scratch (allocation-free). Raw 16-bit payloads (bf16 or fp16 per region).
__device__ __align__(16) unsigned short g_F[(size_t)NTOK * KE];
__device__ __align__(16) unsigned short g_W[(size_t)512 * KE];

__device__ __forceinline__ void cpa16(uint32_t dst, const void* src) {
    asm volatile("cp.async.cg.shared.global [%0], [%1], 16;" :: "r"(dst), "l"(src));
}
__device__ __forceinline__ void ldsm_x4(uint32_t* r, uint32_t addr) {
    asm volatile("ldmatrix.sync.aligned.m8n8.x4.shared.b16 {%0,%1,%2,%3}, [%4];"
                 : "=r"(r[0]), "=r"(r[1]), "=r"(r[2]), "=r"(r[3]) : "r"(addr));
}
__device__ __forceinline__ void mma_bf16_f32(float* c, const uint32_t* a,
                                             uint32_t b0, uint32_t b1) {
    asm volatile("mma.sync.aligned.m16n8k16.row.col.f32.bf16.bf16.f32 "
                 "{%0,%1,%2,%3}, {%4,%5,%6,%7}, {%8,%9}, {%0,%1,%2,%3};"
                 : "+f"(c[0]), "+f"(c[1]), "+f"(c[2]), "+f"(c[3])
                 : "r"(a[0]), "r"(a[1]), "r"(a[2]), "r"(a[3]), "r"(b0), "r"(b1));
}
__device__ __forceinline__ void mma_f16_f16(uint32_t* c, const uint32_t* a,
                                            uint32_t b0, uint32_t b1) {
    asm volatile("mma.sync.aligned.m16n8k16.row.col.f16.f16.f16.f16 "
                 "{%0,%1}, {%2,%3,%4,%5}, {%6,%7}, {%0,%1};"
                 : "+r"(c[0]), "+r"(c[1])
                 : "r"(a[0]), "r"(a[1]), "r"(a[2]), "r"(a[3]), "r"(b0), "r"(b1));
}

// ---------------------------------------------------------------------------
// Kernel 1: LayerNorm + features -> 3-region split A, coalesced 2B stores
// ---------------------------------------------------------------------------
__global__ __launch_bounds__(512)
void feat_kernel(const float* __restrict__ x,
                 const float* __restrict__ gamma_,
                 const float* __restrict__ beta_)
{
    const int tok = blockIdx.x;
    const int d   = threadIdx.x;
    const float v = x[(size_t)tok * DIN + d];

    __shared__ float red1[16], red2[16];

    float s1 = v, s2 = v * v;
    #pragma unroll
    for (int o = 16; o > 0; o >>= 1) {
        s1 += __shfl_xor_sync(0xffffffffu, s1, o);
        s2 += __shfl_xor_sync(0xffffffffu, s2, o);
    }
    if ((d & 31) == 0) { red1[d >> 5] = s1; red2[d >> 5] = s2; }
    __syncthreads();
    if (d < 16) {
        float t1 = red1[d], t2 = red2[d];
        #pragma unroll
        for (int o = 8; o > 0; o >>= 1) {
            t1 += __shfl_xor_sync(0x0000ffffu, t1, o);
            t2 += __shfl_xor_sync(0x0000ffffu, t2, o);
        }
        if (d == 0) { red1[0] = t1; red2[0] = t2; }
    }
    __syncthreads();
    const float mu  = red1[0] * (1.0f / DIN);
    const float var = red2[0] * (1.0f / DIN) - mu * mu;
    const float xn  = (v - mu) * rsqrtf(var + 1e-5f) * gamma_[d] + beta_[d];

    // cubic B-spline on uniform knots
    float b[11];
    #pragma unroll
    for (int i = 0; i < 11; i++) {
        const float t0 = (float)(i - 3) * 0.6f - 1.5f;
        const float t1 = (float)(i - 2) * 0.6f - 1.5f;
        b[i] = (xn >= t0 && xn < t1) ? 1.0f : 0.0f;
    }
    #pragma unroll
    for (int k = 1; k <= 3; k++) {
        #pragma unroll
        for (int i = 0; i < 11 - k; i++) {
            const float ti   = (float)(i - 3)     * 0.6f - 1.5f;
            const float ti1  = (float)(i - 2)     * 0.6f - 1.5f;
            const float tik  = (float)(i + k - 3) * 0.6f - 1.5f;
            const float tik1 = (float)(i + k - 2) * 0.6f - 1.5f;
            b[i] = (xn - ti) * (1.0f / (tik - ti)) * b[i]
                 + (tik1 - xn) * (1.0f / (tik1 - ti1)) * b[i + 1];
        }
    }

    // RBF via two-sided exp-ratio chains (4 expf instead of 9).
    // g_j = exp(-(xh - j)^2), xh in grid coords; chain: g_{j+1} = g_j * e^{2(xh-j)-1}.
    // Left chain underflows for xh >> 0; right chain covers it; fmax picks valid.
    const float xh = (xn + 1.5f) * (7.0f / 3.0f);
    const float C2 = 0.13533528f;   // e^-2
    float rb[8];
    {
        float gl = __expf(-xh * xh);
        float fl = __expf(2.0f * xh - 1.0f);
        #pragma unroll
        for (int j = 0; j < 8; j++) { rb[j] = gl; gl *= fl; fl *= C2; }
        float gr = __expf(-(xh - 7.0f) * (xh - 7.0f));
        float fr = __expf(13.0f - 2.0f * xh);
        #pragma unroll
        for (int j = 7; j >= 0; j--) { rb[j] = fmaxf(rb[j], gr); gr *= fr; fr *= C2; }
    }

    float feat[9];
    feat[0] = fmaxf(xn, 0.0f);
    #pragma unroll
    for (int j = 0; j < NB; j++) feat[1 + j] = b[j] + rb[j];

    // Region layout (k = j*512 + d within each region):
    //   R1 [0,KR):     bf16 hi        R2 [KR,2KR): fp16 lo      R3 [2KR,3KR): fp16 hi
    unsigned short* row = g_F + (size_t)tok * KE;
    #pragma unroll
    for (int j = 0; j < 9; j++) {
        const float f = feat[j];
        const __nv_bfloat16 hi = __float2bfloat16(f);
        const float fhi = __bfloat162float(hi);
        row[j * 512 + d]          = __bfloat16_as_ushort(hi);
        row[KR + j * 512 + d]     = __half_as_ushort(__float2half_rn(f - fhi));
        row[2 * KR + j * 512 + d] = __half_as_ushort(__float2half_rn(fhi));
    }
}

// ---------------------------------------------------------------------------
// Kernel 2: pack weights, mirrored 3-region split
//   R1: bf16(w)   R2: fp16(bf16(w)) [exact cast]   R3: fp16(w - bf16(w))
// ---------------------------------------------------------------------------
__global__ void pack_kernel(const float* __restrict__ bw,
                            const float* __restrict__ sw)
{
    const int idx = blockIdx.x * blockDim.x + threadIdx.x;
    if (idx >= 512 * KE) return;
    const int o  = idx / KE;
    const int ke = idx % KE;
    const int r  = ke / KR;
    const int k  = ke - r * KR;
    const int j  = k >> 9;
    const int d  = k & 511;
    const float w = (j == 0) ? bw[(size_t)o * DIN + d]
                             : sw[(size_t)o * (DIN * NB) + d * NB + (j - 1)];
    const __nv_bfloat16 bh = __float2bfloat16(w);
    const float fbh = __bfloat162float(bh);
    unsigned short bits;
    if (r == 0)      bits = __bfloat16_as_ushort(bh);
    else if (r == 1) bits = __half_as_ushort(__float2half_rn(fbh));
    else             bits = __half_as_ushort(__float2half_rn(w - fbh));
    g_W[idx] = bits;
}

// ---------------------------------------------------------------------------
// Kernel 3: two-phase mma.sync GEMM. Phase A: fp16/f16-acc corrections
// (stages 72..215); convert acc; Phase B: bf16/f32-acc main (stages 0..71).
// CTA 256x128, 8 warps 4Mx2N of 64x64, 4-stage cp.async pipeline.
// ---------------------------------------------------------------------------
__global__ __launch_bounds__(256, 1)
void gemm_kernel(float* __restrict__ C)
{
    extern __shared__ char smem_raw[];
    uint32_t raw;
    asm("{ .reg .u64 t; cvta.to.shared.u64 t, %1; cvt.u32.u64 %0, t; }"
        : "=r"(raw) : "l"(smem_raw));
    const uint32_t base = (raw + 1023) & ~1023u;

    const int tid  = threadIdx.x;
    const int wid  = tid >> 5;
    const int lane = tid & 31;
    const int wm   = wid & 3;
    const int wn   = wid >> 2;
    const int bm   = blockIdx.y * CTA_M;
    const int bn   = blockIdx.x * CTA_N;

    const int ld_r0 = tid >> 3;
    const int ld_c  = tid & 7;

    const int rx  = lane & 7;
    const int hiA = lane >> 4;
    const int hiB = (lane >> 3) & 1;
    uint32_t aoff[4], boff[4];
    #pragma unroll
    for (int mt = 0; mt < 4; mt++)
        aoff[mt] = (uint32_t)(wm * 64 + mt * 16 + (lane & 15)) * 128u;
    #pragma unroll
    for (int p = 0; p < 4; p++)
        boff[p] = 32768u + (uint32_t)(wn * 64 + p * 16 + (lane & 7) + ((lane >> 4) << 3)) * 128u;

    float    acc [4][8][4];
    uint32_t acc2[4][8][2];
    #pragma unroll
    for (int mt = 0; mt < 4; mt++)
        #pragma unroll
        for (int nt = 0; nt < 8; nt++) { acc2[mt][nt][0] = 0u; acc2[mt][nt][1] = 0u; }

    uint32_t fa[2][4][4], fb[2][4][4];

    #define LOAD_STAGE(pidx, SBASE) do {                                        \
        const int ko_ = (pidx) * BK;                                            \
        _Pragma("unroll")                                                       \
        for (int i_ = 0; i_ < 8; i_++) {                                        \
            const int r_ = ld_r0 + i_ * 32;                                     \
            cpa16((SBASE) + r_ * 128 + ((ld_c ^ (r_ & 7)) << 4),                \
                  g_F + (size_t)(bm + r_) * KE + ko_ + ld_c * 8);               \
        }                                                                       \
        _Pragma("unroll")                                                       \
        for (int i_ = 0; i_ < 4; i_++) {                                        \
            const int r_ = ld_r0 + i_ * 32;                                     \
            cpa16((SBASE) + 32768u + r_ * 128 + ((ld_c ^ (r_ & 7)) << 4),       \
                  g_W + (size_t)(bn + r_) * KE + ko_ + ld_c * 8);               \
        }                                                                       \
    } while (0)

    #define LOAD_FRAGS(SBASE, ks_, A_, B_) do {                                 \
        _Pragma("unroll")                                                       \
        for (int mt_ = 0; mt_ < 4; mt_++)                                       \
            ldsm_x4((A_)[mt_], (SBASE) + aoff[mt_] +                            \
                    ((uint32_t)((((ks_) << 1) | hiA) ^ rx) << 4));              \
        _Pragma("unroll")                                                       \
        for (int p_ = 0; p_ < 4; p_++)                                          \
            ldsm_x4((B_)[p_], (SBASE) + boff[p_] +                              \
                    ((uint32_t)((((ks_) << 1) | hiB) ^ rx) << 4));              \
    } while (0)

    #define MMA_ALL_F32(A_, B_) do {                                            \
        _Pragma("unroll")                                                       \
        for (int mt_ = 0; mt_ < 4; mt_++)                                       \
            _Pragma("unroll")                                                   \
            for (int nt_ = 0; nt_ < 8; nt_++) {                                 \
                const uint32_t b0_ = (nt_ & 1) ? (B_)[nt_ >> 1][2] : (B_)[nt_ >> 1][0]; \
                const uint32_t b1_ = (nt_ & 1) ? (B_)[nt_ >> 1][3] : (B_)[nt_ >> 1][1]; \
                mma_bf16_f32(acc[mt_][nt_], (A_)[mt_], b0_, b1_);               \
            }                                                                   \
    } while (0)

    #define MMA_ALL_F16(A_, B_) do {                                            \
        _Pragma("unroll")                                                       \
        for (int mt_ = 0; mt_ < 4; mt_++)                                       \
            _Pragma("unroll")                                                   \
            for (int nt_ = 0; nt_ < 8; nt_++) {                                 \
                const uint32_t b0_ = (nt_ & 1) ? (B_)[nt_ >> 1][2] : (B_)[nt_ >> 1][0]; \
                const uint32_t b1_ = (nt_ & 1) ? (B_)[nt_ >> 1][3] : (B_)[nt_ >> 1][1]; \
                mma_f16_f16(acc2[mt_][nt_], (A_)[mt_], b0_, b1_);               \
            }                                                                   \
    } while (0)

    // stage order: t=0..143 -> phys 72..215 (fp16 regions), t=144..215 -> phys 0..71
    #define PHYS(t_) ((t_) < NF16 ? (t_) + (NST - NF16) : (t_) - NF16)

    #define STEP(tv, BUF, MMA_MACRO) do {                                       \
        const int t_ = (tv);                                                    \
        asm volatile("cp.async.wait_group 2;" ::: "memory");                    \
        __syncthreads();                                                        \
        const uint32_t SA_ = base + (uint32_t)(BUF) * STAGE_BYTES;              \
        LOAD_FRAGS(SA_, 0, fa[0], fb[0]);                                       \
        if (t_ + 3 < NST) {                                                     \
            LOAD_STAGE(PHYS(t_ + 3),                                            \
                       base + (uint32_t)(((BUF) + 3) & 3) * STAGE_BYTES);       \
        }                                                                       \
        asm volatile("cp.async.commit_group;" ::: "memory");                    \
        _Pragma("unroll")                                                       \
        for (int ks_ = 0; ks_ < 4; ks_++) {                                     \
            const int cur_ = ks_ & 1;                                           \
            if (ks_ < 3) LOAD_FRAGS(SA_, ks_ + 1, fa[cur_ ^ 1], fb[cur_ ^ 1]);  \
            MMA_MACRO(fa[cur_], fb[cur_]);                                      \
        }                                                                       \
    } while (0)

    // prologue: t = 0,1,2 -> phys 72,73,74 into bufs 0,1,2
    LOAD_STAGE(PHYS(0), base);
    asm volatile("cp.async.commit_group;" ::: "memory");
    LOAD_STAGE(PHYS(1), base + STAGE_BYTES);
    asm volatile("cp.async.commit_group;" ::: "memory");
    LOAD_STAGE(PHYS(2), base + 2 * STAGE_BYTES);
    asm volatile("cp.async.commit_group;" ::: "memory");

    // Phase A: fp16 corrections, f16 accumulate
    for (int t = 0; t < NF16; t += 4) {
        STEP(t + 0, 0, MMA_ALL_F16);
        STEP(t + 1, 1, MMA_ALL_F16);
        STEP(t + 2, 2, MMA_ALL_F16);
        STEP(t + 3, 3, MMA_ALL_F16);
    }

    // Convert f16 partial sums -> f32 accumulators
    #pragma unroll
    for (int mt = 0; mt < 4; mt++)
        #pragma unroll
        for (int nt = 0; nt < 8; nt++) {
            const __half2 h0 = *reinterpret_cast<const __half2*>(&acc2[mt][nt][0]);
            const __half2 h1 = *reinterpret_cast<const __half2*>(&acc2[mt][nt][1]);
            const float2 f0 = __half22float2(h0);
            const float2 f1 = __half22float2(h1);
            acc[mt][nt][0] = f0.x; acc[mt][nt][1] = f0.y;
            acc[mt][nt][2] = f1.x; acc[mt][nt][3] = f1.y;
        }

    // Phase B: bf16 main term, f32 accumulate (buffer parity continues: 144%4==0)
    for (int t = NF16; t < NST; t += 4) {
        STEP(t + 0, 0, MMA_ALL_F32);
        STEP(t + 1, 1, MMA_ALL_F32);
        STEP(t + 2, 2, MMA_ALL_F32);
        STEP(t + 3, 3, MMA_ALL_F32);
    }

    // epilogue
    const int g  = lane >> 2;
    const int tg = lane & 3;
    #pragma unroll
    for (int mt = 0; mt < 4; mt++) {
        const int row0 = bm + wm * 64 + mt * 16 + g;
        #pragma unroll
        for (int nt = 0; nt < 8; nt++) {
            const int col = bn + wn * 64 + nt * 8 + tg * 2;
            float2 v0; v0.x = acc[mt][nt][0]; v0.y = acc[mt][nt][1];
            float2 v1; v1.x = acc[mt][nt][2]; v1.y = acc[mt][nt][3];
            *(float2*)&C[(size_t)row0 * 512 + col]       = v0;
            *(float2*)&C[(size_t)(row0 + 8) * 512 + col] = v1;
        }
    }
}

// tiny probe kernel: shifts ncu's capture slot so gemm gets profiled
__global__ void probe_kernel() {}

// ---------------------------------------------------------------------------
extern "C" void kernel_launch(void* const* d_in, const int* in_sizes, int n_in,
                              void* d_out, int out_size)
{
    const float* x  = (const float*)d_in[0];
    const float* g  = (const float*)d_in[1];
    const float* bt = (const float*)d_in[2];
    const float* bw = (const float*)d_in[3];
    const float* sw = (const float*)d_in[4];
    float* out = (float*)d_out;

    const int SMEM_DYN = 1024 + 4 * STAGE_BYTES;
    cudaFuncSetAttribute(gemm_kernel, cudaFuncAttributeMaxDynamicSharedMemorySize, SMEM_DYN);

    feat_kernel<<<NTOK, 512>>>(x, g, bt);
    pack_kernel<<<(512 * KE + 255) / 256, 256>>>(bw, sw);
    gemm_kernel<<<dim3(512 / CTA_N, NTOK / CTA_M), 256, SMEM_DYN>>>(out);
    probe_kernel<<<1, 32>>>();
}

// round 9
// speedup vs baseline: 2.3298x; 2.3298x over previous
#include <cuda_runtime.h>
#include <cuda_bf16.h>
#include <cuda_fp16.h>
#include <cstdint>

#define NTOK 16384
#define DIN  512
#define NB   8
#define KR   4608                 // K = 512*9, single fp16 term
#define BK   64                   // K per stage = 128 bytes/row
#define NST  72                   // KR / BK
#define STAGE_BYTES 49152         // A 32KB + B 16KB
#define CTA_M 256
#define CTA_N 128

// Scratch (allocation-free), fp16 payloads
__device__ __align__(16) unsigned short g_F[(size_t)NTOK * KR];
__device__ __align__(16) unsigned short g_W[(size_t)512 * KR];

__device__ __forceinline__ void cpa16(uint32_t dst, const void* src) {
    asm volatile("cp.async.cg.shared.global [%0], [%1], 16;" :: "r"(dst), "l"(src));
}
__device__ __forceinline__ void ldsm_x4(uint32_t* r, uint32_t addr) {
    asm volatile("ldmatrix.sync.aligned.m8n8.x4.shared.b16 {%0,%1,%2,%3}, [%4];"
                 : "=r"(r[0]), "=r"(r[1]), "=r"(r[2]), "=r"(r[3]) : "r"(addr));
}
__device__ __forceinline__ void mma_f16_f32(float* c, const uint32_t* a,
                                            uint32_t b0, uint32_t b1) {
    asm volatile("mma.sync.aligned.m16n8k16.row.col.f32.f16.f16.f32 "
                 "{%0,%1,%2,%3}, {%4,%5,%6,%7}, {%8,%9}, {%0,%1,%2,%3};"
                 : "+f"(c[0]), "+f"(c[1]), "+f"(c[2]), "+f"(c[3])
                 : "r"(a[0]), "r"(a[1]), "r"(a[2]), "r"(a[3]), "r"(b0), "r"(b1));
}

// ---------------------------------------------------------------------------
// Kernel 1: LayerNorm + features -> fp16 A [tok][j*512+d], coalesced stores
// ---------------------------------------------------------------------------
__global__ __launch_bounds__(512)
void feat_kernel(const float* __restrict__ x,
                 const float* __restrict__ gamma_,
                 const float* __restrict__ beta_)
{
    const int tok = blockIdx.x;
    const int d   = threadIdx.x;
    const float v = x[(size_t)tok * DIN + d];

    __shared__ float red1[16], red2[16];

    float s1 = v, s2 = v * v;
    #pragma unroll
    for (int o = 16; o > 0; o >>= 1) {
        s1 += __shfl_xor_sync(0xffffffffu, s1, o);
        s2 += __shfl_xor_sync(0xffffffffu, s2, o);
    }
    if ((d & 31) == 0) { red1[d >> 5] = s1; red2[d >> 5] = s2; }
    __syncthreads();
    if (d < 16) {
        float t1 = red1[d], t2 = red2[d];
        #pragma unroll
        for (int o = 8; o > 0; o >>= 1) {
            t1 += __shfl_xor_sync(0x0000ffffu, t1, o);
            t2 += __shfl_xor_sync(0x0000ffffu, t2, o);
        }
        if (d == 0) { red1[0] = t1; red2[0] = t2; }
    }
    __syncthreads();
    const float mu  = red1[0] * (1.0f / DIN);
    const float var = red2[0] * (1.0f / DIN) - mu * mu;
    const float xn  = (v - mu) * rsqrtf(var + 1e-5f) * gamma_[d] + beta_[d];

    // cubic B-spline on uniform knots
    float b[11];
    #pragma unroll
    for (int i = 0; i < 11; i++) {
        const float t0 = (float)(i - 3) * 0.6f - 1.5f;
        const float t1 = (float)(i - 2) * 0.6f - 1.5f;
        b[i] = (xn >= t0 && xn < t1) ? 1.0f : 0.0f;
    }
    #pragma unroll
    for (int k = 1; k <= 3; k++) {
        #pragma unroll
        for (int i = 0; i < 11 - k; i++) {
            const float ti   = (float)(i - 3)     * 0.6f - 1.5f;
            const float ti1  = (float)(i - 2)     * 0.6f - 1.5f;
            const float tik  = (float)(i + k - 3) * 0.6f - 1.5f;
            const float tik1 = (float)(i + k - 2) * 0.6f - 1.5f;
            b[i] = (xn - ti) * (1.0f / (tik - ti)) * b[i]
                 + (tik1 - xn) * (1.0f / (tik1 - ti1)) * b[i + 1];
        }
    }

    // RBF via two-sided exp-ratio chains (4 expf)
    const float xh = (xn + 1.5f) * (7.0f / 3.0f);
    const float C2 = 0.13533528f;   // e^-2
    float rb[8];
    {
        float gl = __expf(-xh * xh);
        float fl = __expf(2.0f * xh - 1.0f);
        #pragma unroll
        for (int j = 0; j < 8; j++) { rb[j] = gl; gl *= fl; fl *= C2; }
        float gr = __expf(-(xh - 7.0f) * (xh - 7.0f));
        float fr = __expf(13.0f - 2.0f * xh);
        #pragma unroll
        for (int j = 7; j >= 0; j--) { rb[j] = fmaxf(rb[j], gr); gr *= fr; fr *= C2; }
    }

    float feat[9];
    feat[0] = fmaxf(xn, 0.0f);
    #pragma unroll
    for (int j = 0; j < NB; j++) feat[1 + j] = b[j] + rb[j];

    unsigned short* row = g_F + (size_t)tok * KR;
    #pragma unroll
    for (int j = 0; j < 9; j++)
        row[j * 512 + d] = __half_as_ushort(__float2half_rn(feat[j]));
}

// ---------------------------------------------------------------------------
// Kernel 2: pack weights -> fp16 B [o][j*512+d]
// ---------------------------------------------------------------------------
__global__ void pack_kernel(const float* __restrict__ bw,
                            const float* __restrict__ sw)
{
    const int idx = blockIdx.x * blockDim.x + threadIdx.x;
    if (idx >= 512 * KR) return;
    const int o = idx / KR;
    const int k = idx % KR;
    const int j = k >> 9;
    const int d = k & 511;
    const float w = (j == 0) ? bw[(size_t)o * DIN + d]
                             : sw[(size_t)o * (DIN * NB) + d * NB + (j - 1)];
    g_W[idx] = __half_as_ushort(__float2half_rn(w));
}

// ---------------------------------------------------------------------------
// Kernel 3: fp16 mma.sync GEMM  C[16384][512] = A[16384][4608] * B^T
// CTA 256x128, 8 warps 4Mx2N of 64x64, BK=64 SW128, 4-stage cp.async,
// frag double-buffer, static stage bases via x4 unroll.
// ---------------------------------------------------------------------------
__global__ __launch_bounds__(256, 1)
void gemm_kernel(float* __restrict__ C)
{
    extern __shared__ char smem_raw[];
    uint32_t raw;
    asm("{ .reg .u64 t; cvta.to.shared.u64 t, %1; cvt.u32.u64 %0, t; }"
        : "=r"(raw) : "l"(smem_raw));
    const uint32_t base = (raw + 1023) & ~1023u;

    const int tid  = threadIdx.x;
    const int wid  = tid >> 5;
    const int lane = tid & 31;
    const int wm   = wid & 3;
    const int wn   = wid >> 2;
    const int bm   = blockIdx.y * CTA_M;
    const int bn   = blockIdx.x * CTA_N;

    const int ld_r0 = tid >> 3;
    const int ld_c  = tid & 7;

    const int rx  = lane & 7;
    const int hiA = lane >> 4;
    const int hiB = (lane >> 3) & 1;
    uint32_t aoff[4], boff[4];
    #pragma unroll
    for (int mt = 0; mt < 4; mt++)
        aoff[mt] = (uint32_t)(wm * 64 + mt * 16 + (lane & 15)) * 128u;
    #pragma unroll
    for (int p = 0; p < 4; p++)
        boff[p] = 32768u + (uint32_t)(wn * 64 + p * 16 + (lane & 7) + ((lane >> 4) << 3)) * 128u;

    float acc[4][8][4];
    #pragma unroll
    for (int mt = 0; mt < 4; mt++)
        #pragma unroll
        for (int nt = 0; nt < 8; nt++)
            #pragma unroll
            for (int q = 0; q < 4; q++) acc[mt][nt][q] = 0.0f;

    uint32_t fa[2][4][4], fb[2][4][4];

    #define LOAD_STAGE(sidx, SBASE) do {                                        \
        const int ko_ = (sidx) * BK;                                            \
        _Pragma("unroll")                                                       \
        for (int i_ = 0; i_ < 8; i_++) {                                        \
            const int r_ = ld_r0 + i_ * 32;                                     \
            cpa16((SBASE) + r_ * 128 + ((ld_c ^ (r_ & 7)) << 4),                \
                  g_F + (size_t)(bm + r_) * KR + ko_ + ld_c * 8);               \
        }                                                                       \
        _Pragma("unroll")                                                       \
        for (int i_ = 0; i_ < 4; i_++) {                                        \
            const int r_ = ld_r0 + i_ * 32;                                     \
            cpa16((SBASE) + 32768u + r_ * 128 + ((ld_c ^ (r_ & 7)) << 4),       \
                  g_W + (size_t)(bn + r_) * KR + ko_ + ld_c * 8);               \
        }                                                                       \
    } while (0)

    #define LOAD_FRAGS(SBASE, ks_, A_, B_) do {                                 \
        _Pragma("unroll")                                                       \
        for (int mt_ = 0; mt_ < 4; mt_++)                                       \
            ldsm_x4((A_)[mt_], (SBASE) + aoff[mt_] +                            \
                    ((uint32_t)((((ks_) << 1) | hiA) ^ rx) << 4));              \
        _Pragma("unroll")                                                       \
        for (int p_ = 0; p_ < 4; p_++)                                          \
            ldsm_x4((B_)[p_], (SBASE) + boff[p_] +                              \
                    ((uint32_t)((((ks_) << 1) | hiB) ^ rx) << 4));              \
    } while (0)

    #define MMA_ALL(A_, B_) do {                                                \
        _Pragma("unroll")                                                       \
        for (int mt_ = 0; mt_ < 4; mt_++)                                       \
            _Pragma("unroll")                                                   \
            for (int nt_ = 0; nt_ < 8; nt_++) {                                 \
                const uint32_t b0_ = (nt_ & 1) ? (B_)[nt_ >> 1][2] : (B_)[nt_ >> 1][0]; \
                const uint32_t b1_ = (nt_ & 1) ? (B_)[nt_ >> 1][3] : (B_)[nt_ >> 1][1]; \
                mma_f16_f32(acc[mt_][nt_], (A_)[mt_], b0_, b1_);                \
            }                                                                   \
    } while (0)

    #define STEP(sv, BUF) do {                                                  \
        const int s_ = (sv);                                                    \
        asm volatile("cp.async.wait_group 2;" ::: "memory");                    \
        __syncthreads();                                                        \
        const uint32_t SA_ = base + (uint32_t)(BUF) * STAGE_BYTES;              \
        LOAD_FRAGS(SA_, 0, fa[0], fb[0]);                                       \
        if (s_ + 3 < NST) {                                                     \
            LOAD_STAGE(s_ + 3, base + (uint32_t)(((BUF) + 3) & 3) * STAGE_BYTES); \
        }                                                                       \
        asm volatile("cp.async.commit_group;" ::: "memory");                    \
        _Pragma("unroll")                                                       \
        for (int ks_ = 0; ks_ < 4; ks_++) {                                     \
            const int cur_ = ks_ & 1;                                           \
            if (ks_ < 3) LOAD_FRAGS(SA_, ks_ + 1, fa[cur_ ^ 1], fb[cur_ ^ 1]);  \
            MMA_ALL(fa[cur_], fb[cur_]);                                        \
        }                                                                       \
    } while (0)

    // prologue: stages 0..2 into bufs 0..2
    LOAD_STAGE(0, base);
    asm volatile("cp.async.commit_group;" ::: "memory");
    LOAD_STAGE(1, base + STAGE_BYTES);
    asm volatile("cp.async.commit_group;" ::: "memory");
    LOAD_STAGE(2, base + 2 * STAGE_BYTES);
    asm volatile("cp.async.commit_group;" ::: "memory");

    for (int t = 0; t < NST; t += 4) {
        STEP(t + 0, 0);
        STEP(t + 1, 1);
        STEP(t + 2, 2);
        STEP(t + 3, 3);
    }

    // epilogue
    const int g  = lane >> 2;
    const int tg = lane & 3;
    #pragma unroll
    for (int mt = 0; mt < 4; mt++) {
        const int row0 = bm + wm * 64 + mt * 16 + g;
        #pragma unroll
        for (int nt = 0; nt < 8; nt++) {
            const int col = bn + wn * 64 + nt * 8 + tg * 2;
            float2 v0; v0.x = acc[mt][nt][0]; v0.y = acc[mt][nt][1];
            float2 v1; v1.x = acc[mt][nt][2]; v1.y = acc[mt][nt][3];
            *(float2*)&C[(size_t)row0 * 512 + col]       = v0;
            *(float2*)&C[(size_t)(row0 + 8) * 512 + col] = v1;
        }
    }
}

// ---------------------------------------------------------------------------
extern "C" void kernel_launch(void* const* d_in, const int* in_sizes, int n_in,
                              void* d_out, int out_size)
{
    const float* x  = (const float*)d_in[0];
    const float* g  = (const float*)d_in[1];
    const float* bt = (const float*)d_in[2];
    const float* bw = (const float*)d_in[3];
    const float* sw = (const float*)d_in[4];
    float* out = (float*)d_out;

    const int SMEM_DYN = 1024 + 4 * STAGE_BYTES;
    cudaFuncSetAttribute(gemm_kernel, cudaFuncAttributeMaxDynamicSharedMemorySize, SMEM_DYN);

    feat_kernel<<<NTOK, 512>>>(x, g, bt);
    pack_kernel<<<(512 * KR + 255) / 256, 256>>>(bw, sw);
    gemm_kernel<<<dim3(512 / CTA_N, NTOK / CTA_M), 256, SMEM_DYN>>>(out);
}

// round 10
// speedup vs baseline: 2.4271x; 1.0418x over previous
#include <cuda_runtime.h>
#include <cuda_bf16.h>
#include <cuda_fp16.h>
#include <cstdint>

#define NTOK 16384
#define DIN  512
#define NB   8
#define KR   4608                 // K = 512*9, single fp16 term
#define BK   64                   // K per stage = 128 bytes/row
#define NST  72                   // KR / BK
#define STAGE_BYTES 49152         // A 32KB + B 16KB
#define CTA_M 256
#define CTA_N 128

// Scratch (allocation-free), fp16 payloads
__device__ __align__(16) unsigned short g_F[(size_t)NTOK * KR];
__device__ __align__(16) unsigned short g_W[(size_t)512 * KR];

__device__ __forceinline__ void cpa16(uint32_t dst, const void* src) {
    asm volatile("cp.async.cg.shared.global [%0], [%1], 16;" :: "r"(dst), "l"(src));
}
__device__ __forceinline__ void ldsm_x4(uint32_t* r, uint32_t addr) {
    asm volatile("ldmatrix.sync.aligned.m8n8.x4.shared.b16 {%0,%1,%2,%3}, [%4];"
                 : "=r"(r[0]), "=r"(r[1]), "=r"(r[2]), "=r"(r[3]) : "r"(addr));
}
__device__ __forceinline__ void mma_f16_f32(float* c, const uint32_t* a,
                                            uint32_t b0, uint32_t b1) {
    asm volatile("mma.sync.aligned.m16n8k16.row.col.f32.f16.f16.f32 "
                 "{%0,%1,%2,%3}, {%4,%5,%6,%7}, {%8,%9}, {%0,%1,%2,%3};"
                 : "+f"(c[0]), "+f"(c[1]), "+f"(c[2]), "+f"(c[3])
                 : "r"(a[0]), "r"(a[1]), "r"(a[2]), "r"(a[3]), "r"(b0), "r"(b1));
}

// dummy: shifts ncu's capture (launch index 3) onto gemm_kernel
__global__ void shift_kernel() {}

// ---------------------------------------------------------------------------
// Kernel 1: LayerNorm + features -> fp16 A [tok][j*512+d]
// ---------------------------------------------------------------------------
__global__ __launch_bounds__(512)
void feat_kernel(const float* __restrict__ x,
                 const float* __restrict__ gamma_,
                 const float* __restrict__ beta_)
{
    const int tok = blockIdx.x;
    const int d   = threadIdx.x;
    const float v = x[(size_t)tok * DIN + d];

    __shared__ float red1[16], red2[16];

    float s1 = v, s2 = v * v;
    #pragma unroll
    for (int o = 16; o > 0; o >>= 1) {
        s1 += __shfl_xor_sync(0xffffffffu, s1, o);
        s2 += __shfl_xor_sync(0xffffffffu, s2, o);
    }
    if ((d & 31) == 0) { red1[d >> 5] = s1; red2[d >> 5] = s2; }
    __syncthreads();
    if (d < 16) {
        float t1 = red1[d], t2 = red2[d];
        #pragma unroll
        for (int o = 8; o > 0; o >>= 1) {
            t1 += __shfl_xor_sync(0x0000ffffu, t1, o);
            t2 += __shfl_xor_sync(0x0000ffffu, t2, o);
        }
        if (d == 0) { red1[0] = t1; red2[0] = t2; }
    }
    __syncthreads();
    const float mu  = red1[0] * (1.0f / DIN);
    const float var = red2[0] * (1.0f / DIN) - mu * mu;
    const float xn  = (v - mu) * rsqrtf(var + 1e-5f) * gamma_[d] + beta_[d];

    // cubic B-spline via closed-form symmetric kernel:
    // B_j(xn) = [max(2-r,0)^3 - 4*max(1-r,0)^3] / 6,  r = |p - j - 2|
    const float p = (xn + 3.3f) * (1.0f / 0.6f);   // knot-units from t_0
    float b[8];
    #pragma unroll
    for (int j = 0; j < 8; j++) {
        const float r  = fabsf(p - (float)(j + 2));
        const float t2 = fmaxf(2.0f - r, 0.0f);
        const float t1 = fmaxf(1.0f - r, 0.0f);
        const float c2 = t2 * t2 * t2;
        const float c1 = t1 * t1 * t1;
        b[j] = (c2 - 4.0f * c1) * (1.0f / 6.0f);
    }

    // RBF via two-sided exp-ratio chains (4 expf)
    const float xh = (xn + 1.5f) * (7.0f / 3.0f);
    const float C2 = 0.13533528f;   // e^-2
    float rb[8];
    {
        float gl = __expf(-xh * xh);
        float fl = __expf(2.0f * xh - 1.0f);
        #pragma unroll
        for (int j = 0; j < 8; j++) { rb[j] = gl; gl *= fl; fl *= C2; }
        float gr = __expf(-(xh - 7.0f) * (xh - 7.0f));
        float fr = __expf(13.0f - 2.0f * xh);
        #pragma unroll
        for (int j = 7; j >= 0; j--) { rb[j] = fmaxf(rb[j], gr); gr *= fr; fr *= C2; }
    }

    unsigned short* row = g_F + (size_t)tok * KR;
    row[d] = __half_as_ushort(__float2half_rn(fmaxf(xn, 0.0f)));
    #pragma unroll
    for (int j = 0; j < NB; j++)
        row[(1 + j) * 512 + d] = __half_as_ushort(__float2half_rn(b[j] + rb[j]));
}

// ---------------------------------------------------------------------------
// Kernel 2: pack weights -> fp16 B [o][j*512+d]
// ---------------------------------------------------------------------------
__global__ void pack_kernel(const float* __restrict__ bw,
                            const float* __restrict__ sw)
{
    const int idx = blockIdx.x * blockDim.x + threadIdx.x;
    if (idx >= 512 * KR) return;
    const int o = idx / KR;
    const int k = idx % KR;
    const int j = k >> 9;
    const int d = k & 511;
    const float w = (j == 0) ? bw[(size_t)o * DIN + d]
                             : sw[(size_t)o * (DIN * NB) + d * NB + (j - 1)];
    g_W[idx] = __half_as_ushort(__float2half_rn(w));
}

// ---------------------------------------------------------------------------
// Kernel 3: fp16 mma.sync GEMM  C[16384][512] = A[16384][4608] * B^T
// CTA 256x128, 512 threads, 16 warps (4M x 4N) of 64x32 tiles, BK=64 SW128,
// 4-stage cp.async pipeline, single-buffered frags (4 warps/SMSP hide LDS).
// ---------------------------------------------------------------------------
__global__ __launch_bounds__(512, 1)
void gemm_kernel(float* __restrict__ C)
{
    extern __shared__ char smem_raw[];
    uint32_t raw;
    asm("{ .reg .u64 t; cvta.to.shared.u64 t, %1; cvt.u32.u64 %0, t; }"
        : "=r"(raw) : "l"(smem_raw));
    const uint32_t base = (raw + 1023) & ~1023u;

    const int tid  = threadIdx.x;
    const int wid  = tid >> 5;
    const int lane = tid & 31;
    const int wm   = wid & 3;          // 0..3 along M (64 each)
    const int wn   = wid >> 2;         // 0..3 along N (32 each)
    const int bm   = blockIdx.y * CTA_M;
    const int bn   = blockIdx.x * CTA_N;

    // loaders: 512 threads, 64 rows covered per iter
    const int ld_r0 = tid >> 3;        // 0..63
    const int ld_c  = tid & 7;

    const int rx  = lane & 7;
    const int hiA = lane >> 4;
    const int hiB = (lane >> 3) & 1;
    uint32_t aoff[4], boff[2];
    #pragma unroll
    for (int mt = 0; mt < 4; mt++)
        aoff[mt] = (uint32_t)(wm * 64 + mt * 16 + (lane & 15)) * 128u;
    #pragma unroll
    for (int pp = 0; pp < 2; pp++)
        boff[pp] = 32768u + (uint32_t)(wn * 32 + pp * 16 + (lane & 7) + ((lane >> 4) << 3)) * 128u;

    float acc[4][4][4];
    #pragma unroll
    for (int mt = 0; mt < 4; mt++)
        #pragma unroll
        for (int nt = 0; nt < 4; nt++)
            #pragma unroll
            for (int q = 0; q < 4; q++) acc[mt][nt][q] = 0.0f;

    uint32_t fa[4][4], fb[2][4];

    #define LOAD_STAGE(sidx, SBASE) do {                                        \
        const int ko_ = (sidx) * BK;                                            \
        _Pragma("unroll")                                                       \
        for (int i_ = 0; i_ < 4; i_++) {                                        \
            const int r_ = ld_r0 + i_ * 64;                                     \
            cpa16((SBASE) + r_ * 128 + ((ld_c ^ (r_ & 7)) << 4),                \
                  g_F + (size_t)(bm + r_) * KR + ko_ + ld_c * 8);               \
        }                                                                       \
        _Pragma("unroll")                                                       \
        for (int i_ = 0; i_ < 2; i_++) {                                        \
            const int r_ = ld_r0 + i_ * 64;                                     \
            cpa16((SBASE) + 32768u + r_ * 128 + ((ld_c ^ (r_ & 7)) << 4),       \
                  g_W + (size_t)(bn + r_) * KR + ko_ + ld_c * 8);               \
        }                                                                       \
    } while (0)

    #define STEP(sv, BUF) do {                                                  \
        const int s_ = (sv);                                                    \
        asm volatile("cp.async.wait_group 2;" ::: "memory");                    \
        __syncthreads();                                                        \
        const uint32_t SA_ = base + (uint32_t)(BUF) * STAGE_BYTES;              \
        if (s_ + 3 < NST) {                                                     \
            LOAD_STAGE(s_ + 3, base + (uint32_t)(((BUF) + 3) & 3) * STAGE_BYTES); \
        }                                                                       \
        asm volatile("cp.async.commit_group;" ::: "memory");                    \
        _Pragma("unroll")                                                       \
        for (int ks_ = 0; ks_ < 4; ks_++) {                                     \
            _Pragma("unroll")                                                   \
            for (int mt_ = 0; mt_ < 4; mt_++)                                   \
                ldsm_x4(fa[mt_], SA_ + aoff[mt_] +                              \
                        ((uint32_t)(((ks_ << 1) | hiA) ^ rx) << 4));            \
            _Pragma("unroll")                                                   \
            for (int pp_ = 0; pp_ < 2; pp_++)                                   \
                ldsm_x4(fb[pp_], SA_ + boff[pp_] +                              \
                        ((uint32_t)(((ks_ << 1) | hiB) ^ rx) << 4));            \
            _Pragma("unroll")                                                   \
            for (int mt_ = 0; mt_ < 4; mt_++)                                   \
                _Pragma("unroll")                                               \
                for (int nt_ = 0; nt_ < 4; nt_++) {                             \
                    const uint32_t b0_ = (nt_ & 1) ? fb[nt_ >> 1][2] : fb[nt_ >> 1][0]; \
                    const uint32_t b1_ = (nt_ & 1) ? fb[nt_ >> 1][3] : fb[nt_ >> 1][1]; \
                    mma_f16_f32(acc[mt_][nt_], fa[mt_], b0_, b1_);              \
                }                                                               \
        }                                                                       \
    } while (0)

    // prologue: stages 0..2 into bufs 0..2
    LOAD_STAGE(0, base);
    asm volatile("cp.async.commit_group;" ::: "memory");
    LOAD_STAGE(1, base + STAGE_BYTES);
    asm volatile("cp.async.commit_group;" ::: "memory");
    LOAD_STAGE(2, base + 2 * STAGE_BYTES);
    asm volatile("cp.async.commit_group;" ::: "memory");

    for (int t = 0; t < NST; t += 4) {
        STEP(t + 0, 0);
        STEP(t + 1, 1);
        STEP(t + 2, 2);
        STEP(t + 3, 3);
    }

    // epilogue: thread holds rows g, g+8 and cols 2tg, 2tg+1 per (mt, nt)
    const int g  = lane >> 2;
    const int tg = lane & 3;
    #pragma unroll
    for (int mt = 0; mt < 4; mt++) {
        const int row0 = bm + wm * 64 + mt * 16 + g;
        #pragma unroll
        for (int nt = 0; nt < 4; nt++) {
            const int col = bn + wn * 32 + nt * 8 + tg * 2;
            float2 v0; v0.x = acc[mt][nt][0]; v0.y = acc[mt][nt][1];
            float2 v1; v1.x = acc[mt][nt][2]; v1.y = acc[mt][nt][3];
            *(float2*)&C[(size_t)row0 * 512 + col]       = v0;
            *(float2*)&C[(size_t)(row0 + 8) * 512 + col] = v1;
        }
    }
}

// ---------------------------------------------------------------------------
extern "C" void kernel_launch(void* const* d_in, const int* in_sizes, int n_in,
                              void* d_out, int out_size)
{
    const float* x  = (const float*)d_in[0];
    const float* g  = (const float*)d_in[1];
    const float* bt = (const float*)d_in[2];
    const float* bw = (const float*)d_in[3];
    const float* sw = (const float*)d_in[4];
    float* out = (float*)d_out;

    const int SMEM_DYN = 1024 + 4 * STAGE_BYTES;
    cudaFuncSetAttribute(gemm_kernel, cudaFuncAttributeMaxDynamicSharedMemorySize, SMEM_DYN);

    shift_kernel<<<1, 32>>>();                     // launch idx 0 -> ncu idx 3 = gemm
    feat_kernel<<<NTOK, 512>>>(x, g, bt);          // idx 1
    pack_kernel<<<(512 * KR + 255) / 256, 256>>>(bw, sw);  // idx 2
    gemm_kernel<<<dim3(512 / CTA_N, NTOK / CTA_M), 512, SMEM_DYN>>>(out);  // idx 3
}